// round 1
// baseline (speedup 1.0000x reference)
#include <cuda_runtime.h>
#include <cstdint>

// Problem constants
#define CC   32
#define HH   80
#define WW   80
#define KK   4
#define HP   77            // HH-KK+1
#define NP   (HP*HP)       // 5929 patches
#define DD   (CC*KK*KK)    // 512
#define MW   81            // mask width (H+1)
#define EPSF 1e-6f

// ---------------- device scratch (allocation-free rule: __device__ globals) ----
__device__ float              g_lowp [NP * DD];   // candidate patches [P][512]
__device__ float              g_highp[NP * DD];   // query patches     [P][512]
__device__ float              g_invnorm[NP];
__device__ unsigned char      g_excl[NP];
__device__ unsigned char      g_valid[NP];
__device__ unsigned long long g_keys[NP];
__device__ int                g_qlist[NP];
__device__ int                g_qcount;

// monotone float->uint mapping (order-preserving for all finite floats)
__device__ __forceinline__ unsigned mono(float f) {
    unsigned b = __float_as_uint(f);
    return (b & 0x80000000u) ? ~b : (b | 0x80000000u);
}

// ---------------- K0: reset query counter ------------------------------------
__global__ void reset_kernel() { g_qcount = 0; }

// ---------------- K1: extract patch matrices ---------------------------------
__global__ void extract_kernel(const float* __restrict__ low,
                               const float* __restrict__ high) {
    int idx = blockIdx.x * blockDim.x + threadIdx.x;
    if (idx >= NP * DD) return;
    int p  = idx >> 9;        // /512
    int d  = idx & 511;
    int pi = p / HP, pj = p % HP;
    int c  = d >> 4;
    int di = (d >> 2) & 3;
    int dj = d & 3;
    int off = c * (HH * WW) + (pi + di) * WW + (pj + dj);
    g_lowp[idx]  = low[off];
    g_highp[idx] = high[off];
}

// ---------------- K2: per-patch stats (norm, excl, valid, compaction) --------
__global__ void stats_kernel(const int* __restrict__ mask) {
    int gwarp = (blockIdx.x * blockDim.x + threadIdx.x) >> 5;
    int lane  = threadIdx.x & 31;
    if (gwarp >= NP) return;
    const float* row = g_lowp + (size_t)gwarp * DD;
    float s = 0.f;
    #pragma unroll 4
    for (int d = lane; d < DD; d += 32) { float v = row[d]; s += v * v; }
    #pragma unroll
    for (int o = 16; o; o >>= 1) s += __shfl_xor_sync(0xFFFFFFFFu, s, o);
    if (lane == 0) {
        g_invnorm[gwarp] = 1.0f / (sqrtf(s) + EPSF);
        int i = gwarp / HP, j = gwarp % HP;
        g_excl[gwarp] = (mask[i * MW + j] == 1);
        // argmax(all -1e9) == 0 fallback key: score=-1e9, cand=0
        g_keys[gwarp] = ((unsigned long long)0 << 32);
        unsigned long long init =
            ((unsigned long long)mono(-1e9f) << 32) | 0xFFFFFFFFull; // ~cand, cand=0
        g_keys[gwarp] = init;
        int v = (mask[i * MW + j] != 0) && (mask[i * MW + j + KK] != 0) &&
                (mask[(i + KK) * MW + j] != 0) && (mask[(i + KK) * MW + j + KK] != 0);
        g_valid[gwarp] = (unsigned char)v;
        if (v) {
            int slot = atomicAdd(&g_qcount, 1);
            g_qlist[slot] = gwarp;
        }
    }
}

// ---------------- K3: GEMM over valid queries + fused argmax -----------------
// Tile: 64 queries x 64 candidates x K=16, 256 threads, 4x4 per thread (FFMA).
__global__ void __launch_bounds__(256) gemm_argmax_kernel() {
    const int nq = g_qcount;
    const int qb = blockIdx.y;
    if (qb * 64 >= nq) return;           // most query-tiles exit immediately
    const int cb = blockIdx.x;

    __shared__ float As[64][17];
    __shared__ float Bs[64][17];
    __shared__ int   qs[64];
    __shared__ unsigned long long red[64][16];

    const int tid = threadIdx.x;
    if (tid < 64) {
        int qi = qb * 64 + tid;
        qs[tid] = (qi < nq) ? g_qlist[qi] : -1;
    }
    __syncthreads();

    const int ty = tid >> 4, tx = tid & 15;
    float acc[4][4];
    #pragma unroll
    for (int i = 0; i < 4; i++)
        #pragma unroll
        for (int j = 0; j < 4; j++) acc[i][j] = 0.f;

    const int lm = tid >> 2;            // row 0..63 loaded by this thread
    const int lv = (tid & 3) * 4;       // 4-float chunk within K-slab
    const int qlm    = qs[lm];
    const int candlm = cb * 64 + lm;
    const float* arow = (qlm >= 0)   ? g_highp + (size_t)qlm    * DD + lv : g_highp;
    const float* brow = (candlm < NP)? g_lowp  + (size_t)candlm * DD + lv : g_lowp;
    const bool aok = (qlm >= 0), bok = (candlm < NP);

    for (int k0 = 0; k0 < DD; k0 += 16) {
        float4 a = aok ? *(const float4*)(arow + k0) : make_float4(0, 0, 0, 0);
        float4 b = bok ? *(const float4*)(brow + k0) : make_float4(0, 0, 0, 0);
        As[lm][lv + 0] = a.x; As[lm][lv + 1] = a.y; As[lm][lv + 2] = a.z; As[lm][lv + 3] = a.w;
        Bs[lm][lv + 0] = b.x; Bs[lm][lv + 1] = b.y; Bs[lm][lv + 2] = b.z; Bs[lm][lv + 3] = b.w;
        __syncthreads();
        #pragma unroll
        for (int k = 0; k < 16; k++) {
            float af[4], bf[4];
            #pragma unroll
            for (int i = 0; i < 4; i++) af[i] = As[ty * 4 + i][k];
            #pragma unroll
            for (int j = 0; j < 4; j++) bf[j] = Bs[tx * 4 + j][k];
            #pragma unroll
            for (int i = 0; i < 4; i++)
                #pragma unroll
                for (int j = 0; j < 4; j++) acc[i][j] = fmaf(af[i], bf[j], acc[i][j]);
        }
        __syncthreads();
    }

    // epilogue: per-thread best over its 4 candidates, per query row
    #pragma unroll
    for (int i = 0; i < 4; i++) {
        int m = ty * 4 + i;
        unsigned long long best = 0ull;
        if (qs[m] >= 0) {
            #pragma unroll
            for (int j = 0; j < 4; j++) {
                int cand = cb * 64 + tx * 4 + j;
                if (cand < NP && !g_excl[cand]) {
                    float s = acc[i][j] * g_invnorm[cand];
                    unsigned long long key =
                        ((unsigned long long)mono(s) << 32) | (unsigned)(~cand);
                    if (key > best) best = key;
                }
            }
        }
        red[m][tx] = best;
    }
    __syncthreads();
    if (tid < 64) {
        unsigned long long b = red[tid][0];
        #pragma unroll
        for (int t = 1; t < 16; t++) { unsigned long long v = red[tid][t]; if (v > b) b = v; }
        if (b != 0ull && qs[tid] >= 0)
            atomicMax(&g_keys[qs[tid]], b);
    }
}

// ---------------- K4: output assembly (gather-side overlap-average) ----------
__global__ void output_kernel(const float* __restrict__ low,
                              float* __restrict__ out) {
    int idx = blockIdx.x * blockDim.x + threadIdx.x;
    if (idx >= CC * HH * WW) return;
    int c   = idx / (HH * WW);
    int rem = idx - c * (HH * WW);
    int y = rem / WW, x = rem % WW;

    int ilo = y - (KK - 1); if (ilo < 0) ilo = 0;
    int ihi = y; if (ihi > HP - 1) ihi = HP - 1;
    int jlo = x - (KK - 1); if (jlo < 0) jlo = 0;
    int jhi = x; if (jhi > HP - 1) jhi = HP - 1;

    float cnt = 0.f, accv = 0.f;
    for (int i = ilo; i <= ihi; i++) {
        for (int j = jlo; j <= jhi; j++) {
            int p = i * HP + j;
            if (g_valid[p]) {
                cnt += 1.0f;
                unsigned bp = (unsigned)(~g_keys[p]);  // low 32 bits = ~cand
                int bi = bp / HP, bj = bp % HP;
                accv += low[c * (HH * WW) + (bi + y - i) * WW + (bj + x - j)];
            }
        }
    }
    out[idx] = (cnt != 0.f) ? (accv / (cnt + EPSF)) : low[idx];
}

// ---------------- launcher ---------------------------------------------------
extern "C" void kernel_launch(void* const* d_in, const int* in_sizes, int n_in,
                              void* d_out, int out_size) {
    const float* low  = (const float*)d_in[0];
    const float* high = (const float*)d_in[1];
    const int*   mask = (const int*)d_in[2];
    float*       out  = (float*)d_out;

    reset_kernel<<<1, 1>>>();
    extract_kernel<<<(NP * DD + 255) / 256, 256>>>(low, high);
    stats_kernel<<<(NP + 7) / 8, 256>>>(mask);
    gemm_argmax_kernel<<<dim3((NP + 63) / 64, (NP + 63) / 64), 256>>>();
    output_kernel<<<(CC * HH * WW + 255) / 256, 256>>>(low, out);
}